// round 1
// baseline (speedup 1.0000x reference)
#include <cuda_runtime.h>

#define NS  262144
#define C   128
#define KK  27
#define EPSF 1e-4f

#define TM  128     // sites per block tile
#define TC  32      // cin tile

// -------- scratch (device globals; no allocations allowed) --------
__device__ float g_h[NS * C];      // BN-ReLU output (gather source)
__device__ float g_y[NS * C];      // conv1 output
__device__ float g_sum[C];
__device__ float g_sumsq[C];
__device__ float g_scale[C];
__device__ float g_shift[C];

// -------- BN stats --------
__global__ void zero_stats_kernel() {
    int t = threadIdx.x;
    if (t < C) { g_sum[t] = 0.f; g_sumsq[t] = 0.f; }
}

__global__ void bn_stats_kernel(const float* __restrict__ x) {
    // 256 threads/block, 256 rows/block. thread -> fixed channel, 2 threads/channel.
    const int c    = threadIdx.x & (C - 1);
    const int half = threadIdx.x >> 7;
    const int base = blockIdx.x * 256;
    float s = 0.f, s2 = 0.f;
    #pragma unroll 4
    for (int r = half; r < 256; r += 2) {
        float v = x[(base + r) * C + c];
        s += v; s2 += v * v;
    }
    __shared__ float sh[256], sh2[256];
    sh[threadIdx.x] = s; sh2[threadIdx.x] = s2;
    __syncthreads();
    if (half == 0) {
        atomicAdd(&g_sum[c],   sh[threadIdx.x]  + sh[threadIdx.x + 128]);
        atomicAdd(&g_sumsq[c], sh2[threadIdx.x] + sh2[threadIdx.x + 128]);
    }
}

__global__ void bn_finalize_kernel(const float* __restrict__ gamma,
                                   const float* __restrict__ beta) {
    int c = threadIdx.x;
    if (c < C) {
        float mu  = g_sum[c]   * (1.f / (float)NS);
        float var = g_sumsq[c] * (1.f / (float)NS) - mu * mu;
        float sc  = gamma[c] * rsqrtf(var + EPSF);
        g_scale[c] = sc;
        g_shift[c] = beta[c] - mu * sc;
    }
}

__global__ void bn_apply_kernel(const float4* __restrict__ x,
                                float4* __restrict__ o) {
    int i  = blockIdx.x * blockDim.x + threadIdx.x;   // over NS*C/4
    int c4 = (i & 31) << 2;
    float4 v = x[i];
    float s0 = g_scale[c4+0], s1 = g_scale[c4+1], s2 = g_scale[c4+2], s3 = g_scale[c4+3];
    float t0 = g_shift[c4+0], t1 = g_shift[c4+1], t2 = g_shift[c4+2], t3 = g_shift[c4+3];
    float4 r;
    r.x = fmaxf(fmaf(v.x, s0, t0), 0.f);
    r.y = fmaxf(fmaf(v.y, s1, t1), 0.f);
    r.z = fmaxf(fmaf(v.z, s2, t2), 0.f);
    r.w = fmaxf(fmaf(v.w, s3, t3), 0.f);
    o[i] = r;
}

// -------- submanifold conv: out[m,:] = bias + sum_k mask * h[nbr[m,k]] @ W[k] (+residual) --------
__global__ void __launch_bounds__(256, 2)
conv_kernel(const float* __restrict__ h,
            const int*   __restrict__ nbr_idx,
            const int*   __restrict__ nbr_mask,
            const float* __restrict__ W,       // [K, C, C]
            const float* __restrict__ bias,    // [C]
            const float* __restrict__ residual,// [NS, C] or null
            float*       __restrict__ out)
{
    __shared__ int   s_idx[TM * KK];           // premultiplied row offset, or -1 if masked
    __shared__ float s_a[TM][TC + 4];          // gathered A tile
    __shared__ float s_w[TC][C];               // W tile

    const int tid = threadIdx.x;
    const int m0  = blockIdx.x * TM;

    for (int i = tid; i < TM * KK; i += 256) {
        int gi  = m0 * KK + i;
        int msk = nbr_mask[gi];
        s_idx[i] = msk ? (nbr_idx[gi] * C) : -1;
    }

    const int ty = tid >> 4;     // 0..15 : rows ty*8..ty*8+7
    const int tx = tid & 15;     // 0..15 : cols tx*8..tx*8+7

    float acc[8][8];
    #pragma unroll
    for (int j = 0; j < 8; j++) {
        float b = bias[tx * 8 + j];
        #pragma unroll
        for (int i = 0; i < 8; i++) acc[i][j] = b;
    }

    const int a_row = tid >> 3;        // 0..31, +32*q
    const int a_col = tid & 7;         // float4 index within 32 cin
    const int w_row = tid >> 5;        // 0..7, +8*q
    const int w_col = tid & 31;        // float4 index within 128 cout

    for (int k = 0; k < KK; k++) {
        const float* Wk = W + k * C * C;
        for (int ci = 0; ci < C; ci += TC) {
            __syncthreads();
            // gather A tile: TM x TC (masked rows -> 0)
            #pragma unroll
            for (int q = 0; q < 4; q++) {
                int row  = a_row + 32 * q;
                int gidx = s_idx[row * KK + k];
                float4 v = make_float4(0.f, 0.f, 0.f, 0.f);
                if (gidx >= 0)
                    v = *(const float4*)&h[gidx + ci + a_col * 4];
                *(float4*)&s_a[row][a_col * 4] = v;
            }
            // W tile: TC x C
            #pragma unroll
            for (int q = 0; q < 4; q++) {
                int j = w_row + 8 * q;
                *(float4*)&s_w[j][w_col * 4] =
                    *(const float4*)&Wk[(ci + j) * C + w_col * 4];
            }
            __syncthreads();
            // 8x8 micro-tile FMA
            #pragma unroll
            for (int j = 0; j < TC; j++) {
                float a[8];
                #pragma unroll
                for (int i = 0; i < 8; i++) a[i] = s_a[ty * 8 + i][j];
                float4 b0 = *(const float4*)&s_w[j][tx * 8];
                float4 b1 = *(const float4*)&s_w[j][tx * 8 + 4];
                float b[8] = { b0.x, b0.y, b0.z, b0.w, b1.x, b1.y, b1.z, b1.w };
                #pragma unroll
                for (int i = 0; i < 8; i++)
                    #pragma unroll
                    for (int jj = 0; jj < 8; jj++)
                        acc[i][jj] = fmaf(a[i], b[jj], acc[i][jj]);
            }
        }
    }

    // epilogue (+optional residual), vectorized stores
    #pragma unroll
    for (int i = 0; i < 8; i++) {
        int m = m0 + ty * 8 + i;
        float* orow = out + m * C + tx * 8;
        float4 o0 = make_float4(acc[i][0], acc[i][1], acc[i][2], acc[i][3]);
        float4 o1 = make_float4(acc[i][4], acc[i][5], acc[i][6], acc[i][7]);
        if (residual) {
            const float* rrow = residual + m * C + tx * 8;
            float4 r0 = *(const float4*)rrow;
            float4 r1 = *(const float4*)(rrow + 4);
            o0.x += r0.x; o0.y += r0.y; o0.z += r0.z; o0.w += r0.w;
            o1.x += r1.x; o1.y += r1.y; o1.z += r1.z; o1.w += r1.w;
        }
        *(float4*)orow       = o0;
        *(float4*)(orow + 4) = o1;
    }
}

// -------- launch --------
extern "C" void kernel_launch(void* const* d_in, const int* in_sizes, int n_in,
                              void* d_out, int out_size)
{
    const float* features = (const float*)d_in[0];
    const int*   nbr_idx  = (const int*)  d_in[1];
    const int*   nbr_mask = (const int*)  d_in[2];
    const float* gamma1   = (const float*)d_in[3];
    const float* beta1    = (const float*)d_in[4];
    const float* W1       = (const float*)d_in[5];
    const float* bias1    = (const float*)d_in[6];
    const float* gamma2   = (const float*)d_in[7];
    const float* beta2    = (const float*)d_in[8];
    const float* W2       = (const float*)d_in[9];
    const float* bias2    = (const float*)d_in[10];
    float* out = (float*)d_out;

    float *h_ptr, *y_ptr;
    cudaGetSymbolAddress((void**)&h_ptr, g_h);
    cudaGetSymbolAddress((void**)&y_ptr, g_y);

    const int stats_grid = NS / 256;
    const int apply_grid = (NS * C / 4) / 256;
    const int conv_grid  = NS / TM;

    // ---- layer 1 ----
    zero_stats_kernel<<<1, 256>>>();
    bn_stats_kernel<<<stats_grid, 256>>>(features);
    bn_finalize_kernel<<<1, 128>>>(gamma1, beta1);
    bn_apply_kernel<<<apply_grid, 256>>>((const float4*)features, (float4*)h_ptr);
    conv_kernel<<<conv_grid, 256>>>(h_ptr, nbr_idx, nbr_mask, W1, bias1, nullptr, y_ptr);

    // ---- layer 2 (+ residual into output) ----
    zero_stats_kernel<<<1, 256>>>();
    bn_stats_kernel<<<stats_grid, 256>>>(y_ptr);
    bn_finalize_kernel<<<1, 128>>>(gamma2, beta2);
    bn_apply_kernel<<<apply_grid, 256>>>((const float4*)y_ptr, (float4*)h_ptr);
    conv_kernel<<<conv_grid, 256>>>(h_ptr, nbr_idx, nbr_mask, W2, bias2, features, out);
}

// round 3
// speedup vs baseline: 3.0172x; 3.0172x over previous
#include <cuda_runtime.h>
#include <cstdint>

#define NS   262144
#define C    128
#define KK   27
#define EPSF 1e-4f

#define CTA_M    256
#define PIPE     3
#define NSTAGE   (KK * 4)          // 108 stages: k x 4 cin-chunks of 32
#define A_STRIDE 36                // floats per A row in smem (pad for banks)
#define W_STRIDE 40                // floats per W col row in smem (pad for banks)
#define A_BYTES  (CTA_M * A_STRIDE * 4)   // 36864
#define W_BYTES  (C * W_STRIDE * 4)       // 20480
#define DSMEM_TOTAL (PIPE * (A_BYTES + W_BYTES))   // 172032

// ===================== scratch (device globals) =====================
__device__ float g_h[NS * C];            // BN-ReLU output, tf32-rounded
__device__ float g_y[NS * C];            // conv1 output (fp32)
__device__ float g_wt1[KK * C * C];      // W1 permuted to B-fragment layout
__device__ float g_wt2[KK * C * C];
__device__ float g_sum[C];
__device__ float g_sumsq[C];
__device__ float g_scale[C];
__device__ float g_shift[C];

// ===================== helpers =====================
__device__ __forceinline__ uint32_t smem_u32(const void* p) {
    uint32_t a;
    asm("{ .reg .u64 t; cvta.to.shared.u64 t, %1; cvt.u32.u64 %0, t; }"
        : "=r"(a) : "l"(p));
    return a;
}

__device__ __forceinline__ float tf32_round(float x) {
    uint32_t u;
    asm("cvt.rna.tf32.f32 %0, %1;" : "=r"(u) : "f"(x));
    return __uint_as_float(u);
}

__device__ __forceinline__ void cp_async16(uint32_t dst, const void* src, uint32_t sz) {
    asm volatile("cp.async.cg.shared.global [%0], [%1], 16, %2;"
                 :: "r"(dst), "l"(src), "r"(sz) : "memory");
}
#define CP_COMMIT() asm volatile("cp.async.commit_group;" ::: "memory")
#define CP_WAIT(n)  asm volatile("cp.async.wait_group %0;" :: "n"(n) : "memory")

__device__ __forceinline__ void mma_tf32(float* c,
                                         uint32_t a0, uint32_t a1, uint32_t a2, uint32_t a3,
                                         uint32_t b0, uint32_t b1) {
    asm volatile(
        "mma.sync.aligned.m16n8k8.row.col.f32.tf32.tf32.f32 "
        "{%0,%1,%2,%3}, {%4,%5,%6,%7}, {%8,%9}, {%0,%1,%2,%3};"
        : "+f"(c[0]), "+f"(c[1]), "+f"(c[2]), "+f"(c[3])
        : "r"(a0), "r"(a1), "r"(a2), "r"(a3), "r"(b0), "r"(b1));
}

// ===================== BN kernels =====================
__global__ void zero_stats_kernel() {
    int t = threadIdx.x;
    if (t < C) { g_sum[t] = 0.f; g_sumsq[t] = 0.f; }
}

__global__ void bn_stats_kernel(const float* __restrict__ x) {
    const int c    = threadIdx.x & (C - 1);
    const int half = threadIdx.x >> 7;
    const int base = blockIdx.x * 256;
    float s = 0.f, s2 = 0.f;
    #pragma unroll 4
    for (int r = half; r < 256; r += 2) {
        float v = x[(base + r) * C + c];
        s += v; s2 += v * v;
    }
    __shared__ float sh[256], sh2[256];
    sh[threadIdx.x] = s; sh2[threadIdx.x] = s2;
    __syncthreads();
    if (half == 0) {
        atomicAdd(&g_sum[c],   sh[threadIdx.x]  + sh[threadIdx.x + 128]);
        atomicAdd(&g_sumsq[c], sh2[threadIdx.x] + sh2[threadIdx.x + 128]);
    }
}

__global__ void bn_finalize_kernel(const float* __restrict__ gamma,
                                   const float* __restrict__ beta) {
    int c = threadIdx.x;
    if (c < C) {
        float mu  = g_sum[c]   * (1.f / (float)NS);
        float var = g_sumsq[c] * (1.f / (float)NS) - mu * mu;
        float sc  = gamma[c] * rsqrtf(var + EPSF);
        g_scale[c] = sc;
        g_shift[c] = beta[c] - mu * sc;
    }
}

// BN + ReLU + tf32 round, fused
__global__ void bn_apply_pack_kernel(const float4* __restrict__ x,
                                     float4* __restrict__ o) {
    int i  = blockIdx.x * blockDim.x + threadIdx.x;   // over NS*C/4
    int c4 = (i & 31) << 2;
    float4 v = x[i];
    float4 r;
    r.x = tf32_round(fmaxf(fmaf(v.x, g_scale[c4+0], g_shift[c4+0]), 0.f));
    r.y = tf32_round(fmaxf(fmaf(v.y, g_scale[c4+1], g_shift[c4+1]), 0.f));
    r.z = tf32_round(fmaxf(fmaf(v.z, g_scale[c4+2], g_shift[c4+2]), 0.f));
    r.w = tf32_round(fmaxf(fmaf(v.w, g_scale[c4+3], g_shift[c4+3]), 0.f));
    o[i] = r;
}

// W[k][cin][cout] -> g_wt[k][ch][col][pos], pos encodes (s,c,d) pair layout
// so one LDS.64 per B fragment: pos = s*8 + c*2 + d, cin = ch*32 + s*8 + c + 4d
__global__ void pack_w_kernel(const float* __restrict__ W,
                              float* __restrict__ wt) {
    int o = blockIdx.x * blockDim.x + threadIdx.x;    // KK*C*C
    int pos = o & 31;
    int col = (o >> 5) & 127;
    int ch  = (o >> 12) & 3;
    int k   = o >> 14;
    int s = pos >> 3, c = (pos >> 1) & 3, d = pos & 1;
    int cin = ch * 32 + s * 8 + c + 4 * d;
    wt[o] = tf32_round(W[(k * C + cin) * C + col]);
}

// ===================== tf32 mma.sync gather-GEMM conv =====================
__global__ void __launch_bounds__(256, 1)
conv_mma_kernel(const float* __restrict__ h,
                const int*   __restrict__ nbr_idx,
                const int*   __restrict__ nbr_mask,
                const float* __restrict__ wt,
                const float* __restrict__ bias,
                const float* __restrict__ residual,
                float*       __restrict__ out)
{
    extern __shared__ char dsm[];
    float* smA = (float*)dsm;                               // PIPE x A
    float* smW = (float*)(dsm + PIPE * A_BYTES);            // PIPE x W
    __shared__ int   s_idx[CTA_M * KK];
    __shared__ float s_bias[C];

    const int tid  = threadIdx.x;
    const int warp = tid >> 5;
    const int lane = tid & 31;
    const int m0   = blockIdx.x * CTA_M;

    const uint32_t smA_u = smem_u32(smA);
    const uint32_t smW_u = smem_u32(smW);

    // idx: sign bit = valid, low bits = nbr*C
    for (int i = tid; i < CTA_M * KK; i += 256) {
        int gi = m0 * KK + i;
        s_idx[i] = nbr_mask[gi] ? (int)((uint32_t)(nbr_idx[gi] * C) | 0x80000000u) : 0;
    }
    if (tid < C) s_bias[tid] = bias[tid];
    __syncthreads();

    // warp tiling: 4 M-warps x 2 N-warps, warp tile 64x64
    const int mw = warp & 3;
    const int nw = warp >> 2;
    const int lr = lane >> 2;        // 0..7
    const int lc = lane & 3;         // 0..3

    float acc[4][8][4];
    #pragma unroll
    for (int a = 0; a < 4; a++)
        #pragma unroll
        for (int b = 0; b < 8; b++)
            #pragma unroll
            for (int q = 0; q < 4; q++) acc[a][b][q] = 0.f;

    // stage issue lambda
    const int wcol = tid & 127;
    const int wjb  = tid >> 7;       // 0/1
    auto issue = [&](int st, int p) {
        int k  = st >> 2;
        int ch = st & 3;
        // A gather: thread -> its row
        int v = s_idx[tid * KK + k];
        uint32_t sz = (v < 0) ? 16u : 0u;
        const float* src = h + (v & 0x7FFFFFFF) + ch * 32;
        uint32_t dst = smA_u + p * A_BYTES + tid * (A_STRIDE * 4);
        #pragma unroll
        for (int j = 0; j < 8; j++) cp_async16(dst + j * 16, src + j * 4, sz);
        // W copy (already permuted + tf32 in gmem)
        const float* wsrc = wt + ((size_t)(k * 4 + ch) * C + wcol) * 32 + wjb * 16;
        uint32_t wdst = smW_u + p * W_BYTES + wcol * (W_STRIDE * 4) + wjb * 64;
        #pragma unroll
        for (int j = 0; j < 4; j++) cp_async16(wdst + j * 16, wsrc + j * 4, 16u);
        CP_COMMIT();
    };

    issue(0, 0);
    issue(1, 1);

    for (int st = 0; st < NSTAGE; st++) {
        const int p = st % PIPE;
        if (st + 2 < NSTAGE) { issue(st + 2, (st + 2) % PIPE); CP_WAIT(2); }
        else if (st + 1 < NSTAGE) { CP_WAIT(1); }
        else { CP_WAIT(0); }
        __syncthreads();

        const float* A  = smA + p * (CTA_M * A_STRIDE);
        const float* Wp = smW + p * (C * W_STRIDE);
        const int r0 = mw * 64 + lr;
        const int cb = nw * 64 + lr;

        #pragma unroll
        for (int s = 0; s < 4; s++) {
            uint32_t af[4][4];
            #pragma unroll
            for (int mf = 0; mf < 4; mf++) {
                int rr = r0 + mf * 16;
                af[mf][0] = __float_as_uint(A[rr * A_STRIDE + s * 8 + lc]);
                af[mf][1] = __float_as_uint(A[(rr + 8) * A_STRIDE + s * 8 + lc]);
                af[mf][2] = __float_as_uint(A[rr * A_STRIDE + s * 8 + lc + 4]);
                af[mf][3] = __float_as_uint(A[(rr + 8) * A_STRIDE + s * 8 + lc + 4]);
            }
            #pragma unroll
            for (int nf = 0; nf < 8; nf++) {
                float2 bv = *(const float2*)&Wp[(cb + nf * 8) * W_STRIDE + s * 8 + lc * 2];
                uint32_t b0 = __float_as_uint(bv.x);
                uint32_t b1 = __float_as_uint(bv.y);
                #pragma unroll
                for (int mf = 0; mf < 4; mf++)
                    mma_tf32(acc[mf][nf], af[mf][0], af[mf][1], af[mf][2], af[mf][3], b0, b1);
            }
        }
        __syncthreads();
    }

    // ---- epilogue: acc -> out (+bias, +residual) ----
    #pragma unroll
    for (int mf = 0; mf < 4; mf++) {
        int row = m0 + mw * 64 + mf * 16 + lr;
        #pragma unroll
        for (int nf = 0; nf < 8; nf++) {
            int col = nw * 64 + nf * 8 + lc * 2;
            float2 v0, v1;
            v0.x = acc[mf][nf][0] + s_bias[col];
            v0.y = acc[mf][nf][1] + s_bias[col + 1];
            v1.x = acc[mf][nf][2] + s_bias[col];
            v1.y = acc[mf][nf][3] + s_bias[col + 1];
            if (residual) {
                float2 r0v = *(const float2*)&residual[(size_t)row * C + col];
                float2 r1v = *(const float2*)&residual[(size_t)(row + 8) * C + col];
                v0.x += r0v.x; v0.y += r0v.y;
                v1.x += r1v.x; v1.y += r1v.y;
            }
            *(float2*)&out[(size_t)row * C + col]       = v0;
            *(float2*)&out[(size_t)(row + 8) * C + col] = v1;
        }
    }
}

// ===================== launch =====================
extern "C" void kernel_launch(void* const* d_in, const int* in_sizes, int n_in,
                              void* d_out, int out_size)
{
    const float* features = (const float*)d_in[0];
    const int*   nbr_idx  = (const int*)  d_in[1];
    const int*   nbr_mask = (const int*)  d_in[2];
    const float* gamma1   = (const float*)d_in[3];
    const float* beta1    = (const float*)d_in[4];
    const float* W1       = (const float*)d_in[5];
    const float* bias1    = (const float*)d_in[6];
    const float* gamma2   = (const float*)d_in[7];
    const float* beta2    = (const float*)d_in[8];
    const float* W2       = (const float*)d_in[9];
    const float* bias2    = (const float*)d_in[10];
    float* out = (float*)d_out;

    float *h_ptr, *y_ptr, *wt1_ptr, *wt2_ptr;
    cudaGetSymbolAddress((void**)&h_ptr,   g_h);
    cudaGetSymbolAddress((void**)&y_ptr,   g_y);
    cudaGetSymbolAddress((void**)&wt1_ptr, g_wt1);
    cudaGetSymbolAddress((void**)&wt2_ptr, g_wt2);

    cudaFuncSetAttribute(conv_mma_kernel,
                         cudaFuncAttributeMaxDynamicSharedMemorySize, DSMEM_TOTAL);

    const int stats_grid = NS / 256;
    const int apply_grid = (NS * C / 4) / 256;
    const int packw_grid = (KK * C * C) / 256;
    const int conv_grid  = NS / CTA_M;

    pack_w_kernel<<<packw_grid, 256>>>(W1, wt1_ptr);
    pack_w_kernel<<<packw_grid, 256>>>(W2, wt2_ptr);

    // ---- layer 1 ----
    zero_stats_kernel<<<1, 256>>>();
    bn_stats_kernel<<<stats_grid, 256>>>(features);
    bn_finalize_kernel<<<1, 128>>>(gamma1, beta1);
    bn_apply_pack_kernel<<<apply_grid, 256>>>((const float4*)features, (float4*)h_ptr);
    conv_mma_kernel<<<conv_grid, 256, DSMEM_TOTAL>>>(h_ptr, nbr_idx, nbr_mask,
                                                     wt1_ptr, bias1, nullptr, y_ptr);

    // ---- layer 2 (+ residual) ----
    zero_stats_kernel<<<1, 256>>>();
    bn_stats_kernel<<<stats_grid, 256>>>(y_ptr);
    bn_finalize_kernel<<<1, 128>>>(gamma2, beta2);
    bn_apply_pack_kernel<<<apply_grid, 256>>>((const float4*)y_ptr, (float4*)h_ptr);
    conv_mma_kernel<<<conv_grid, 256, DSMEM_TOTAL>>>(h_ptr, nbr_idx, nbr_mask,
                                                     wt2_ptr, bias2, features, out);
}

// round 5
// speedup vs baseline: 5.6364x; 1.8681x over previous
#include <cuda_runtime.h>
#include <cuda_fp16.h>
#include <cstdint>

#define NS   262144
#define C    128
#define KK   27
#define EPSF 1e-4f

#define CTA_M    256
#define PIPE     3
#define NSTAGE   (KK * 2)            // 54 stages: k x 2 cin-chunks of 64
#define A_ROWB   128                 // bytes per A row (64 halves), XOR-swizzled
#define A_BYTES  (CTA_M * A_ROWB)    // 32768
#define W_STRIDEB 160                // bytes per W col (64 halves + pad)
#define W_BYTES  (C * W_STRIDEB)     // 20480
#define DSMEM_TOTAL (PIPE * (A_BYTES + W_BYTES))   // 159744

// ===================== scratch (device globals) =====================
__device__ __half g_h[NS * C];        // BN-ReLU output, fp16, NATURAL channel order
__device__ float  g_y[NS * C];        // conv1 output (fp32)
__device__ __half g_wt1[KK * C * C];  // W1 permuted to B-fragment layout
__device__ __half g_wt2[KK * C * C];
__device__ float  g_sum[C];
__device__ float  g_sumsq[C];
__device__ float  g_scale[C];
__device__ float  g_shift[C];

// ===================== helpers =====================
__device__ __forceinline__ uint32_t smem_u32(const void* p) {
    uint32_t a;
    asm("{ .reg .u64 t; cvta.to.shared.u64 t, %1; cvt.u32.u64 %0, t; }"
        : "=r"(a) : "l"(p));
    return a;
}

__device__ __forceinline__ void cp_async16(uint32_t dst, const void* src, uint32_t sz) {
    asm volatile("cp.async.cg.shared.global [%0], [%1], 16, %2;"
                 :: "r"(dst), "l"(src), "r"(sz) : "memory");
}
#define CP_COMMIT() asm volatile("cp.async.commit_group;" ::: "memory")
#define CP_WAIT(n)  asm volatile("cp.async.wait_group %0;" :: "n"(n) : "memory")

__device__ __forceinline__ void ldmatrix_x4(uint32_t* r, uint32_t addr) {
    asm volatile("ldmatrix.sync.aligned.m8n8.x4.shared.b16 {%0,%1,%2,%3}, [%4];"
                 : "=r"(r[0]), "=r"(r[1]), "=r"(r[2]), "=r"(r[3]) : "r"(addr));
}

__device__ __forceinline__ void mma_f16(float* c, const uint32_t* a,
                                        uint32_t b0, uint32_t b1) {
    asm volatile(
        "mma.sync.aligned.m16n8k16.row.col.f32.f16.f16.f32 "
        "{%0,%1,%2,%3}, {%4,%5,%6,%7}, {%8,%9}, {%0,%1,%2,%3};"
        : "+f"(c[0]), "+f"(c[1]), "+f"(c[2]), "+f"(c[3])
        : "r"(a[0]), "r"(a[1]), "r"(a[2]), "r"(a[3]), "r"(b0), "r"(b1));
}

// ===================== BN kernels =====================
__global__ void zero_stats_kernel() {
    int t = threadIdx.x;
    if (t < C) { g_sum[t] = 0.f; g_sumsq[t] = 0.f; }
}

__global__ void bn_stats_kernel(const float* __restrict__ x) {
    const int c    = threadIdx.x & (C - 1);
    const int half = threadIdx.x >> 7;
    const int base = blockIdx.x * 256;
    float s = 0.f, s2 = 0.f;
    #pragma unroll 4
    for (int r = half; r < 256; r += 2) {
        float v = x[(base + r) * C + c];
        s += v; s2 += v * v;
    }
    __shared__ float sh[256], sh2[256];
    sh[threadIdx.x] = s; sh2[threadIdx.x] = s2;
    __syncthreads();
    if (half == 0) {
        atomicAdd(&g_sum[c],   sh[threadIdx.x]  + sh[threadIdx.x + 128]);
        atomicAdd(&g_sumsq[c], sh2[threadIdx.x] + sh2[threadIdx.x + 128]);
    }
}

__global__ void bn_finalize_kernel(const float* __restrict__ gamma,
                                   const float* __restrict__ beta) {
    int c = threadIdx.x;
    if (c < C) {
        float mu  = g_sum[c]   * (1.f / (float)NS);
        float var = g_sumsq[c] * (1.f / (float)NS) - mu * mu;
        float sc  = gamma[c] * rsqrtf(var + EPSF);
        g_scale[c] = sc;
        g_shift[c] = beta[c] - mu * sc;
    }
}

// BN + ReLU + fp16 pack, NATURAL channel order (ldmatrix consumes k in smem order)
__global__ void bn_apply_pack_kernel(const float4* __restrict__ x,
                                     __half2* __restrict__ o) {
    int i  = blockIdx.x * blockDim.x + threadIdx.x;   // over NS*C/4
    int c4 = (i & 31) << 2;
    float4 v = x[i];
    float r0 = fmaxf(fmaf(v.x, g_scale[c4+0], g_shift[c4+0]), 0.f);
    float r1 = fmaxf(fmaf(v.y, g_scale[c4+1], g_shift[c4+1]), 0.f);
    float r2 = fmaxf(fmaf(v.z, g_scale[c4+2], g_shift[c4+2]), 0.f);
    float r3 = fmaxf(fmaf(v.w, g_scale[c4+3], g_shift[c4+3]), 0.f);
    o[i * 2 + 0] = __floats2half2_rn(r0, r1);
    o[i * 2 + 1] = __floats2half2_rn(r2, r3);
}

// W[k][cin][cout] -> g_wt[(k*2+ch)][col][pos].
// Within each 16-k group (s), lane lc's LDS.64 at halves [lc*4, lc*4+4) must
// yield k = 2lc, 2lc+1 (b0) and 2lc+8, 2lc+9 (b1), matching natural-order A.
__global__ void pack_w_kernel(const float* __restrict__ W,
                              __half* __restrict__ wt) {
    int o = blockIdx.x * blockDim.x + threadIdx.x;    // KK*C*C
    int pos = o & 63;
    int col = (o >> 6) & 127;
    int kc  = o >> 13;
    int ch  = kc & 1;
    int k   = kc >> 1;
    int s = pos >> 4, q = pos & 15;
    int c = q >> 2,  d = q & 3;
    int krel = (d < 2) ? (2 * c + d) : (8 + 2 * c + (d - 2));
    int cin = ch * 64 + s * 16 + krel;
    wt[o] = __float2half_rn(W[(k * C + cin) * C + col]);
}

// ===================== fp16 mma.sync gather-GEMM conv =====================
__global__ void __launch_bounds__(256, 1)
conv_mma_kernel(const __half* __restrict__ h,
                const int*    __restrict__ nbr_idx,
                const int*    __restrict__ nbr_mask,
                const __half* __restrict__ wt,
                const float*  __restrict__ bias,
                const float*  __restrict__ residual,
                float*        __restrict__ out)
{
    extern __shared__ char dsm[];
    __shared__ int   s_idx[CTA_M * KK];
    __shared__ float s_bias[C];

    const int tid  = threadIdx.x;
    const int warp = tid >> 5;
    const int lane = tid & 31;
    const int m0   = blockIdx.x * CTA_M;

    const uint32_t smA_u = smem_u32(dsm);
    const uint32_t smW_u = smA_u + PIPE * A_BYTES;

    // idx: sign bit = valid, low bits = nbr*C (halves)
    for (int i = tid; i < CTA_M * KK; i += 256) {
        int gi = m0 * KK + i;
        s_idx[i] = nbr_mask[gi] ? (int)((uint32_t)(nbr_idx[gi] * C) | 0x80000000u) : 0;
    }
    if (tid < C) s_bias[tid] = bias[tid];
    __syncthreads();

    // warp tiling: 4 M-warps x 2 N-warps, warp tile 64x64
    const int mw = warp & 3;
    const int nw = warp >> 2;
    const int lr = lane >> 2;        // 0..7
    const int lc = lane & 3;         // 0..3
    // ldmatrix lane mapping: quadrants -> (rows 0-7/8-15) x (k-half 0/1)
    const int gq = lane >> 3;        // 0..3
    const int gl = lane & 7;
    const int rowl = (gq & 1) * 8 + gl;
    const int ghi  = gq >> 1;

    float acc[4][8][4];
    #pragma unroll
    for (int a = 0; a < 4; a++)
        #pragma unroll
        for (int b = 0; b < 8; b++)
            #pragma unroll
            for (int q = 0; q < 4; q++) acc[a][b][q] = 0.f;

    const int wcol = tid & 127;
    const int wjb  = tid >> 7;       // 0/1 : which 32-half half of the col
    const int swA  = (tid & 7) << 4; // XOR swizzle term for own-row stores

    auto issue = [&](int st, int p) {
        const int k  = st >> 1;
        const int ch = st & 1;
        // A gather: thread -> its row (128B, 8 x 16B chunks, swizzled)
        int v = s_idx[tid * KK + k];
        uint32_t sz = (v < 0) ? 16u : 0u;
        const __half* src = h + (v & 0x7FFFFFFF) + ch * 64;
        uint32_t dstrow = smA_u + p * A_BYTES + tid * A_ROWB;
        #pragma unroll
        for (int j = 0; j < 8; j++)
            cp_async16(dstrow + ((j << 4) ^ swA), src + j * 8, sz);
        // W copy (already permuted fp16 in gmem)
        const __half* wsrc = wt + ((size_t)(k * 2 + ch) * C + wcol) * 64 + wjb * 32;
        uint32_t wdst = smW_u + p * W_BYTES + wcol * W_STRIDEB + wjb * 64;
        #pragma unroll
        for (int j = 0; j < 4; j++)
            cp_async16(wdst + j * 16, wsrc + j * 8, 16u);
        CP_COMMIT();
    };

    issue(0, 0);
    issue(1, 1);

    for (int st = 0; st < NSTAGE; st++) {
        const int p = st % PIPE;
        if (st + 2 < NSTAGE) { issue(st + 2, (st + 2) % PIPE); CP_WAIT(2); }
        else if (st + 1 < NSTAGE) { CP_WAIT(1); }
        else { CP_WAIT(0); }
        __syncthreads();

        const uint32_t Abase = smA_u + p * A_BYTES;
        const uint32_t Wbase = smW_u + p * W_BYTES +
                               (nw * 64 + lr) * W_STRIDEB + lc * 8;

        #pragma unroll
        for (int s = 0; s < 4; s++) {
            uint32_t af[4][4];
            #pragma unroll
            for (int mf = 0; mf < 4; mf++) {
                int row = mw * 64 + mf * 16 + rowl;
                uint32_t addr = Abase + row * A_ROWB +
                                ((((s << 1) | ghi) ^ (row & 7)) << 4);
                ldmatrix_x4(af[mf], addr);
            }
            #pragma unroll
            for (int nf = 0; nf < 8; nf++) {
                uint32_t b0, b1;
                uint32_t baddr = Wbase + nf * (8 * W_STRIDEB) + s * 32;
                asm volatile("ld.shared.v2.b32 {%0,%1}, [%2];"
                             : "=r"(b0), "=r"(b1) : "r"(baddr));
                #pragma unroll
                for (int mf = 0; mf < 4; mf++)
                    mma_f16(acc[mf][nf], af[mf], b0, b1);
            }
        }
        __syncthreads();
    }

    // ---- epilogue: acc -> out (+bias, +residual) ----
    #pragma unroll
    for (int mf = 0; mf < 4; mf++) {
        int row = m0 + mw * 64 + mf * 16 + lr;
        #pragma unroll
        for (int nf = 0; nf < 8; nf++) {
            int col = nw * 64 + nf * 8 + lc * 2;
            float2 v0, v1;
            v0.x = acc[mf][nf][0] + s_bias[col];
            v0.y = acc[mf][nf][1] + s_bias[col + 1];
            v1.x = acc[mf][nf][2] + s_bias[col];
            v1.y = acc[mf][nf][3] + s_bias[col + 1];
            if (residual) {
                float2 r0v = *(const float2*)&residual[(size_t)row * C + col];
                float2 r1v = *(const float2*)&residual[(size_t)(row + 8) * C + col];
                v0.x += r0v.x; v0.y += r0v.y;
                v1.x += r1v.x; v1.y += r1v.y;
            }
            *(float2*)&out[(size_t)row * C + col]       = v0;
            *(float2*)&out[(size_t)(row + 8) * C + col] = v1;
        }
    }
}

// ===================== launch =====================
extern "C" void kernel_launch(void* const* d_in, const int* in_sizes, int n_in,
                              void* d_out, int out_size)
{
    const float* features = (const float*)d_in[0];
    const int*   nbr_idx  = (const int*)  d_in[1];
    const int*   nbr_mask = (const int*)  d_in[2];
    const float* gamma1   = (const float*)d_in[3];
    const float* beta1    = (const float*)d_in[4];
    const float* W1       = (const float*)d_in[5];
    const float* bias1    = (const float*)d_in[6];
    const float* gamma2   = (const float*)d_in[7];
    const float* beta2    = (const float*)d_in[8];
    const float* W2       = (const float*)d_in[9];
    const float* bias2    = (const float*)d_in[10];
    float* out = (float*)d_out;

    __half *h_ptr, *wt1_ptr, *wt2_ptr;
    float* y_ptr;
    cudaGetSymbolAddress((void**)&h_ptr,   g_h);
    cudaGetSymbolAddress((void**)&y_ptr,   g_y);
    cudaGetSymbolAddress((void**)&wt1_ptr, g_wt1);
    cudaGetSymbolAddress((void**)&wt2_ptr, g_wt2);

    cudaFuncSetAttribute(conv_mma_kernel,
                         cudaFuncAttributeMaxDynamicSharedMemorySize, DSMEM_TOTAL);

    const int stats_grid = NS / 256;
    const int apply_grid = (NS * C / 4) / 256;
    const int packw_grid = (KK * C * C) / 256;
    const int conv_grid  = NS / CTA_M;

    pack_w_kernel<<<packw_grid, 256>>>(W1, wt1_ptr);
    pack_w_kernel<<<packw_grid, 256>>>(W2, wt2_ptr);

    // ---- layer 1 ----
    zero_stats_kernel<<<1, 256>>>();
    bn_stats_kernel<<<stats_grid, 256>>>(features);
    bn_finalize_kernel<<<1, 128>>>(gamma1, beta1);
    bn_apply_pack_kernel<<<apply_grid, 256>>>((const float4*)features, (__half2*)h_ptr);
    conv_mma_kernel<<<conv_grid, 256, DSMEM_TOTAL>>>(h_ptr, nbr_idx, nbr_mask,
                                                     wt1_ptr, bias1, nullptr, y_ptr);

    // ---- layer 2 (+ residual) ----
    zero_stats_kernel<<<1, 256>>>();
    bn_stats_kernel<<<stats_grid, 256>>>(y_ptr);
    bn_finalize_kernel<<<1, 128>>>(gamma2, beta2);
    bn_apply_pack_kernel<<<apply_grid, 256>>>((const float4*)y_ptr, (__half2*)h_ptr);
    conv_mma_kernel<<<conv_grid, 256, DSMEM_TOTAL>>>(h_ptr, nbr_idx, nbr_mask,
                                                     wt2_ptr, bias2, features, out);
}